// round 3
// baseline (speedup 1.0000x reference)
#include <cuda_runtime.h>
#include <math.h>

// ---------------- problem constants ----------------
#define KS    11
#define HI    384
#define HO    512
#define HOUT  (HO - KS + 1)     // 502
#define TW    32                // tile width (outputs)
#define TH    64                // tile height (outputs)
#define PW    (TW + KS - 1)     // 42
#define PH    (TH + KS - 1)     // 74
#define SW    43                // s12 row stride (ull), conflict-free
#define HS    34                // hbuf row stride
#define NTX   ((HOUT + TW - 1) / TW)   // 16
#define NTY   ((HOUT + TH - 1) / TH)   // 8

typedef unsigned long long ull;

// Gaussian weights (sigma=1.5, ks=11), double-normalized, rounded to f32.
#define GW0  0.0010283801f
#define GW1  0.0075987582f
#define GW2  0.0360007722f
#define GW3  0.1093606884f
#define GW4  0.2130055383f
#define GW5  0.2660117256f

__device__ double        g_accum = 0.0;
__device__ unsigned int  g_count = 0;

// ---------------- f32x2 packed helpers ----------------
__device__ __forceinline__ ull splat2(float g) {
    ull r; asm("mov.b64 %0, {%1, %1};" : "=l"(r) : "f"(g)); return r;
}
__device__ __forceinline__ void up2(ull v, float& lo, float& hi) {
    asm("mov.b64 {%0, %1}, %2;" : "=f"(lo), "=f"(hi) : "l"(v));
}
__device__ __forceinline__ ull pk2(float lo, float hi) {
    ull r; asm("mov.b64 %0, {%1, %2};" : "=l"(r) : "f"(lo), "f"(hi)); return r;
}
__device__ __forceinline__ ull pfma(ull a, ull b, ull c) {
    ull d; asm("fma.rn.f32x2 %0, %1, %2, %3;" : "=l"(d) : "l"(a), "l"(b), "l"(c)); return d;
}
__device__ __forceinline__ ull pmul(ull a, ull b) {
    ull d; asm("mul.rn.f32x2 %0, %1, %2;" : "=l"(d) : "l"(a), "l"(b)); return d;
}

// dynamic smem layout (bytes)
#define OFF_S12   0
#define OFF_HMU   (OFF_S12 + PH * SW * 8)          // 25456
#define OFF_HSQ   (OFF_HMU + PH * HS * 8)          // 45584
#define OFF_HX12  (OFF_HSQ + PH * HS * 8)          // 65712
#define OFF_RED   (OFF_HX12 + PH * HS * 4)         // 75776
#define SMEM_BYTES (OFF_RED + 128)                 // 75904

// ---------------- single fused kernel ----------------
__global__ void __launch_bounds__(256, 3)
ssim_tile_kernel(const float* __restrict__ input,   // [96, 384, 384]
                 const float* __restrict__ target,  // [96, 512, 512]
                 float* __restrict__ out,
                 long long count, unsigned int nblocks)
{
    extern __shared__ char smem[];
    ull   (*s12)[SW]  = (ull (*)[SW])(smem + OFF_S12);
    ull   (*hmu)[HS]  = (ull (*)[HS])(smem + OFF_HMU);
    ull   (*hsq)[HS]  = (ull (*)[HS])(smem + OFF_HSQ);
    float (*hx12)[HS] = (float (*)[HS])(smem + OFF_HX12);
    float *redbuf     = (float*)(smem + OFF_RED);

    const int img = blockIdx.z;
    const int ty0 = blockIdx.y * TH;
    const int tx0 = blockIdx.x * TW;
    const int tid = threadIdx.x;

    const float GW[KS] = {GW0, GW1, GW2, GW3, GW4, GW5, GW4, GW3, GW2, GW1, GW0};
    ull CS[KS];
    #pragma unroll
    for (int k = 0; k < KS; k++) CS[k] = splat2(GW[k]);

    const float* inp = input  + (size_t)img * (HI * HI);
    const float* tgt = target + (size_t)img * (HO * HO);

    // ---- load: target direct, img1 bilinear (exact integer index math) ----
    for (int e = tid; e < PH * PW; e += 256) {
        int r = e / PW;
        int c = e - r * PW;
        int gy = min(ty0 + r, HO - 1);
        int gx = min(tx0 + c, HO - 1);

        float t2 = tgt[gy * HO + gx];

        int py  = gy * (HI - 1);
        int iy0 = py / (HO - 1);
        float wy = (float)(py - iy0 * (HO - 1)) * (1.0f / (float)(HO - 1));
        int iy1 = min(iy0 + 1, HI - 1);
        int px  = gx * (HI - 1);
        int ix0 = px / (HO - 1);
        float wx = (float)(px - ix0 * (HO - 1)) * (1.0f / (float)(HO - 1));
        int ix1 = min(ix0 + 1, HI - 1);

        float a  = inp[iy0 * HI + ix0];
        float b  = inp[iy0 * HI + ix1];
        float cc = inp[iy1 * HI + ix0];
        float d  = inp[iy1 * HI + ix1];
        float top = a  * (1.0f - wx) + b * wx;
        float bot = cc * (1.0f - wx) + d * wx;
        float v1  = top * (1.0f - wy) + bot * wy;

        s12[r][c] = pk2(v1, t2);
    }
    __syncthreads();

    // ---- horizontal pass: 4 output cols per task, sliding 14-tap window ----
    for (int e = tid; e < PH * 8; e += 256) {
        int r  = e >> 3;
        int c0 = (e & 7) << 2;

        ull aM[4] = {0, 0, 0, 0};
        ull aS[4] = {0, 0, 0, 0};
        float aX[4] = {0.f, 0.f, 0.f, 0.f};

        #pragma unroll
        for (int j = 0; j < 14; j++) {
            ull pk = s12[r][c0 + j];
            float p1, p2;
            up2(pk, p1, p2);
            ull sq = pmul(pk, pk);
            float p12 = p1 * p2;
            #pragma unroll
            for (int o = 0; o < 4; o++) {
                int k = j - o;
                if (k >= 0 && k < KS) {
                    aM[o] = pfma(pk, CS[k], aM[o]);
                    aS[o] = pfma(sq, CS[k], aS[o]);
                    aX[o] = fmaf(GW[k], p12, aX[o]);
                }
            }
        }
        #pragma unroll
        for (int o = 0; o < 4; o++) {
            hmu[r][c0 + o]  = aM[o];
            hsq[r][c0 + o]  = aS[o];
            hx12[r][c0 + o] = aX[o];
        }
    }
    __syncthreads();

    // ---- vertical pass: 8 output rows per thread, sliding 18-tap window ----
    const int lx = tid & 31;
    const int o0 = (tid >> 5) << 3;     // warp w -> rows 8w..8w+7

    ull aM[8], aS[8];
    float aX[8];
    #pragma unroll
    for (int o = 0; o < 8; o++) { aM[o] = 0; aS[o] = 0; aX[o] = 0.f; }

    #pragma unroll
    for (int rel = 0; rel < 18; rel++) {
        int rr = o0 + rel;
        ull vM   = hmu[rr][lx];
        ull vS   = hsq[rr][lx];
        float vX = hx12[rr][lx];
        #pragma unroll
        for (int o = 0; o < 8; o++) {
            int k = rel - o;
            if (k >= 0 && k < KS) {
                aM[o] = pfma(vM, CS[k], aM[o]);
                aS[o] = pfma(vS, CS[k], aS[o]);
                aX[o] = fmaf(GW[k], vX, aX[o]);
            }
        }
    }

    // ---- SSIM map + local sum ----
    const float C1 = 1e-4f;
    const float C2 = 9e-4f;
    float lsum = 0.f;
    const int gx = tx0 + lx;

    #pragma unroll
    for (int o = 0; o < 8; o++) {
        int gy = ty0 + o0 + o;
        if (gy < HOUT && gx < HOUT) {
            float mu1, mu2, x11, x22;
            up2(aM[o], mu1, mu2);
            up2(aS[o], x11, x22);
            float mu1sq = mu1 * mu1;
            float mu2sq = mu2 * mu2;
            float mu12  = mu1 * mu2;
            float sig1  = x11 - mu1sq;
            float sig2  = x22 - mu2sq;
            float sig12 = aX[o] - mu12;
            float v1 = 2.0f * sig12 + C2;
            float v2 = sig1 + sig2 + C2;
            float num = (2.0f * mu12 + C1) * v1;
            float den = (mu1sq + mu2sq + C1) * v2;
            lsum += __fdividef(num, den);
        }
    }

    // ---- block reduction ----
    #pragma unroll
    for (int off = 16; off > 0; off >>= 1)
        lsum += __shfl_down_sync(0xFFFFFFFFu, lsum, off);
    int lane = tid & 31;
    int wid  = tid >> 5;
    if (lane == 0) redbuf[wid] = lsum;
    __syncthreads();
    if (tid == 0) {
        float v = 0.f;
        #pragma unroll
        for (int w = 0; w < 8; w++) v += redbuf[w];
        atomicAdd(&g_accum, (double)v);
        __threadfence();
        unsigned int old = atomicAdd(&g_count, 1u);
        if (old == nblocks - 1u) {
            // last block: finalize and reset state for next (graph) replay
            double mean = g_accum / (double)count;
            double loss = 1.0 - mean;
            if (loss < 0.0) loss = 0.0;
            if (loss > 1.0) loss = 1.0;
            out[0] = (float)loss;
            g_accum = 0.0;
            g_count = 0u;
        }
    }
}

extern "C" void kernel_launch(void* const* d_in, const int* in_sizes, int n_in,
                              void* d_out, int out_size) {
    const float* input  = (const float*)d_in[0];
    const float* target = (const float*)d_in[1];
    int sz0 = in_sizes[0], sz1 = in_sizes[1];
    if (sz0 > sz1) {
        const float* t = input; input = target; target = t;
        int ts = sz0; sz0 = sz1; sz1 = ts;
    }
    int n_img = sz0 / (HI * HI);   // 96

    static bool attr_set = false;
    if (!attr_set) {
        cudaFuncSetAttribute(ssim_tile_kernel,
                             cudaFuncAttributeMaxDynamicSharedMemorySize, SMEM_BYTES);
        attr_set = true;
    }

    dim3 grid(NTX, NTY, n_img);
    unsigned int nblocks = NTX * NTY * (unsigned int)n_img;
    long long count = (long long)n_img * HOUT * HOUT;

    ssim_tile_kernel<<<grid, 256, SMEM_BYTES>>>(input, target, (float*)d_out,
                                                count, nblocks);
}